// round 1
// baseline (speedup 1.0000x reference)
#include <cuda_runtime.h>
#include <math.h>

#define NN 50000
#define EE 800000
#define FF 64

// ---- scratch (static device globals; allocation-free) ----
__device__ float g_S [NN * FF];        // up-projected scalars  [N,64]
__device__ float g_V [NN * FF * 3];    // up-projected vectors  [N,64,3]
__device__ float g_AS[NN * FF];        // aggregated scalar messages
__device__ float g_AV[NN * FF * 3];    // aggregated vector messages

// ============================================================================
// Kernel A: linear-up (s = nfs@Wu_s, v = nfv@Wu_v) + zero aggregation buffers
// block = 256 threads = 4 nodes x 64 channels
// ============================================================================
__global__ __launch_bounds__(256) void k_up(
    const float* __restrict__ nfs, const float* __restrict__ nfv,
    const float* __restrict__ Wus, const float* __restrict__ Wuv, int N)
{
    __shared__ float ws[64 * 64];
    __shared__ float wv[64 * 64];
    __shared__ float in_s[4][64];
    __shared__ float in_v[4][192];

    for (int i = threadIdx.x; i < 4096; i += 256) { ws[i] = Wus[i]; wv[i] = Wuv[i]; }
    __syncthreads();

    int slot = threadIdx.x >> 6;
    int g    = threadIdx.x & 63;

    for (int base = blockIdx.x * 4; base < N; base += gridDim.x * 4) {
        int n = base + slot;
        bool valid = (n < N);
        if (valid) {
            in_s[slot][g] = nfs[n * 64 + g];
            in_v[slot][g * 3 + 0] = nfv[n * 192 + g * 3 + 0];
            in_v[slot][g * 3 + 1] = nfv[n * 192 + g * 3 + 1];
            in_v[slot][g * 3 + 2] = nfv[n * 192 + g * 3 + 2];
        }
        __syncthreads();
        if (valid) {
            float a = 0.f, v0 = 0.f, v1 = 0.f, v2 = 0.f;
            #pragma unroll 8
            for (int f = 0; f < 64; f++) {
                float w1 = ws[f * 64 + g];
                float w2 = wv[f * 64 + g];
                a  = fmaf(in_s[slot][f], w1, a);
                v0 = fmaf(in_v[slot][f * 3 + 0], w2, v0);
                v1 = fmaf(in_v[slot][f * 3 + 1], w2, v1);
                v2 = fmaf(in_v[slot][f * 3 + 2], w2, v2);
            }
            g_S[n * 64 + g] = a;
            g_V[n * 192 + g * 3 + 0] = v0;
            g_V[n * 192 + g * 3 + 1] = v1;
            g_V[n * 192 + g * 3 + 2] = v2;
            g_AS[n * 64 + g] = 0.f;
            g_AV[n * 192 + g * 3 + 0] = 0.f;
            g_AV[n * 192 + g * 3 + 1] = 0.f;
            g_AV[n * 192 + g * 3 + 2] = 0.f;
        }
        __syncthreads();
    }
}

// ============================================================================
// Kernel B: edges. Radial MLP (8->64 silu ->320) fused with tensor-product
// messages + atomic scatter. One warp processes 4 edges per iteration.
// Thread lane c owns channels (2c, 2c+1).
// Dynamic smem: W_r2 [64*320] + W_r1 [8*64] + h staging [8 warps][4][64]
// ============================================================================
__global__ __launch_bounds__(256) void k_edge(
    const float* __restrict__ vectors, const float* __restrict__ RE,
    const float* __restrict__ Wr1, const float* __restrict__ Wr2,
    const int* __restrict__ senders, const int* __restrict__ receivers, int En)
{
    extern __shared__ float sm[];
    float* wr2  = sm;                 // 20480 floats
    float* wr1  = sm + 20480;         // 512 floats
    float* hbuf = sm + 20480 + 512;   // 8*4*64 = 2048 floats

    // stage weights (coalesced float4)
    {
        const float4* src = (const float4*)Wr2;
        float4*       dst = (float4*)wr2;
        for (int i = threadIdx.x; i < 20480 / 4; i += 256) dst[i] = src[i];
        for (int i = threadIdx.x; i < 512; i += 256) wr1[i] = Wr1[i];
    }
    __syncthreads();

    int warp = threadIdx.x >> 5;
    int lane = threadIdx.x & 31;
    float* hw = hbuf + warp * 256;    // [4][64]

    int ntiles = (En + 3) >> 2;
    for (int tile = blockIdx.x * 8 + warp; tile < ntiles; tile += gridDim.x * 8) {
        int e0 = tile * 4;

        // ---- layer 1: h[e][j] = silu(sum_k re[e,k] * W_r1[k,j]) ----
        int le = lane >> 3, lk = lane & 7;
        int eg = e0 + le;
        float reK = (eg < En) ? RE[eg * 8 + lk] : 0.f;
        #pragma unroll
        for (int e = 0; e < 4; e++) {
            float a0 = 0.f, a1 = 0.f;
            #pragma unroll
            for (int k = 0; k < 8; k++) {
                float r = __shfl_sync(0xffffffffu, reK, e * 8 + k);
                a0 = fmaf(r, wr1[k * 64 + lane], a0);
                a1 = fmaf(r, wr1[k * 64 + 32 + lane], a1);
            }
            hw[e * 64 + lane]      = __fdividef(a0, 1.f + __expf(-a0));
            hw[e * 64 + 32 + lane] = __fdividef(a1, 1.f + __expf(-a1));
        }
        __syncwarp();

        // ---- layer 2: w[e][p][2c..2c+1] = sum_j h[e][j] * W_r2[j][p*64+2c..] ----
        float acc[4][5][2];
        #pragma unroll
        for (int e = 0; e < 4; e++)
            #pragma unroll
            for (int p = 0; p < 5; p++) { acc[e][p][0] = 0.f; acc[e][p][1] = 0.f; }

        const float2* wr2v = (const float2*)wr2;
        for (int j = 0; j < 64; j += 4) {
            float4 h0 = *(const float4*)(hw + 0 * 64 + j);
            float4 h1 = *(const float4*)(hw + 1 * 64 + j);
            float4 h2 = *(const float4*)(hw + 2 * 64 + j);
            float4 h3 = *(const float4*)(hw + 3 * 64 + j);
            #pragma unroll
            for (int jj = 0; jj < 4; jj++) {
                float hh0 = (&h0.x)[jj], hh1 = (&h1.x)[jj];
                float hh2 = (&h2.x)[jj], hh3 = (&h3.x)[jj];
                #pragma unroll
                for (int p = 0; p < 5; p++) {
                    float2 w = wr2v[(j + jj) * 160 + p * 32 + lane];
                    acc[0][p][0] = fmaf(hh0, w.x, acc[0][p][0]);
                    acc[0][p][1] = fmaf(hh0, w.y, acc[0][p][1]);
                    acc[1][p][0] = fmaf(hh1, w.x, acc[1][p][0]);
                    acc[1][p][1] = fmaf(hh1, w.y, acc[1][p][1]);
                    acc[2][p][0] = fmaf(hh2, w.x, acc[2][p][0]);
                    acc[2][p][1] = fmaf(hh2, w.y, acc[2][p][1]);
                    acc[3][p][0] = fmaf(hh3, w.x, acc[3][p][0]);
                    acc[3][p][1] = fmaf(hh3, w.y, acc[3][p][1]);
                }
            }
        }

        // ---- messages + scatter ----
        #pragma unroll
        for (int e = 0; e < 4; e++) {
            int edge = e0 + e;
            if (edge < En) {
                int s = senders[edge];
                int r = receivers[edge];
                float vx = vectors[edge * 3 + 0];
                float vy = vectors[edge * 3 + 1];
                float vz = vectors[edge * 3 + 2];
                float nrm = sqrtf(vx * vx + vy * vy + vz * vz);
                float ri = 1.f / (nrm + 1e-9f);
                float Y0 = vx * ri, Y1 = vy * ri, Y2 = vz * ri;

                const float2* Sp = (const float2*)(g_S + (size_t)s * 64);
                float2 xs = Sp[lane];
                const float2* Vp = (const float2*)(g_V + (size_t)s * 192);
                float2 p0 = Vp[lane * 3 + 0];
                float2 p1 = Vp[lane * 3 + 1];
                float2 p2 = Vp[lane * 3 + 2];
                float a0 = p0.x, a1 = p0.y, a2 = p1.x;   // channel 2c vector
                float b0 = p1.y, b1 = p2.x, b2 = p2.y;   // channel 2c+1 vector

                float dota = a0 * Y0 + a1 * Y1 + a2 * Y2;
                float dotb = b0 * Y0 + b1 * Y1 + b2 * Y2;

                float w0a = acc[e][0][0], w0b = acc[e][0][1];
                float w1a = acc[e][1][0], w1b = acc[e][1][1];
                float w2a = acc[e][2][0], w2b = acc[e][2][1];
                float w3a = acc[e][3][0], w3b = acc[e][3][1];
                float w4a = acc[e][4][0], w4b = acc[e][4][1];

                float msa = w0a * xs.x + w3a * dota;
                float msb = w0b * xs.y + w3b * dotb;

                // cross(xv, Y)
                float cxa0 = a1 * Y2 - a2 * Y1;
                float cxa1 = a2 * Y0 - a0 * Y2;
                float cxa2 = a0 * Y1 - a1 * Y0;
                float cxb0 = b1 * Y2 - b2 * Y1;
                float cxb1 = b2 * Y0 - b0 * Y2;
                float cxb2 = b0 * Y1 - b1 * Y0;

                float sa = w1a * xs.x, sb = w1b * xs.y;
                float mva0 = sa * Y0 + w2a * a0 + w4a * cxa0;
                float mva1 = sa * Y1 + w2a * a1 + w4a * cxa1;
                float mva2 = sa * Y2 + w2a * a2 + w4a * cxa2;
                float mvb0 = sb * Y0 + w2b * b0 + w4b * cxb0;
                float mvb1 = sb * Y1 + w2b * b1 + w4b * cxb1;
                float mvb2 = sb * Y2 + w2b * b2 + w4b * cxb2;

                float* as = g_AS + (size_t)r * 64 + 2 * lane;
                atomicAdd(as + 0, msa);
                atomicAdd(as + 1, msb);
                float* av = g_AV + (size_t)r * 192 + 6 * lane;
                atomicAdd(av + 0, mva0);
                atomicAdd(av + 1, mva1);
                atomicAdd(av + 2, mva2);
                atomicAdd(av + 3, mvb0);
                atomicAdd(av + 4, mvb1);
                atomicAdd(av + 5, mvb2);
            }
        }
    }
}

// ============================================================================
// Kernel C: node post-processing. linear-down * 1/sqrt(16), symmetric
// contraction, linear + species skip, readout.
// block = 256 threads = 4 nodes x 64 channels. Dynamic smem.
// ============================================================================
__global__ __launch_bounds__(256) void k_node(
    const float* __restrict__ nfs, const float* __restrict__ nfv,
    const float* __restrict__ Wds, const float* __restrict__ Wdv,
    const float* __restrict__ wsym_s, const float* __restrict__ wsym_v,
    const float* __restrict__ WLs, const float* __restrict__ WLv,
    const float* __restrict__ Wsk_s, const float* __restrict__ Wsk_v,
    const float* __restrict__ Wout, const int* __restrict__ specie,
    float* __restrict__ out0, float* __restrict__ fsO, float* __restrict__ fvO,
    int N)
{
    extern __shared__ float sm[];
    float* wds  = sm;               // 4096
    float* wdv  = sm + 4096;        // 4096
    float* wls  = sm + 8192;        // 4096
    float* wlv  = sm + 12288;       // 4096
    float* wout = sm + 16384;       // 64
    float* aggs = sm + 16448;       // 4*64   (reused later for fs staging)
    float* aggv = sm + 16448 + 256; // 4*192
    float* nss  = sm + 16448 + 1024;// 4*64
    float* nvv  = sm + 16448 + 1280;// 4*192
    float* psb  = sm + 16448 + 2048;// 4*64
    float* pvb  = sm + 16448 + 2304;// 4*192  (end: 16448+3072 = 19520 floats)

    for (int i = threadIdx.x; i < 4096; i += 256) {
        wds[i] = Wds[i]; wdv[i] = Wdv[i]; wls[i] = WLs[i]; wlv[i] = WLv[i];
    }
    if (threadIdx.x < 64) wout[threadIdx.x] = Wout[threadIdx.x];
    __syncthreads();

    int slot = threadIdx.x >> 6;
    int g    = threadIdx.x & 63;
    const float inv = 0.25f;  // 1/sqrt(16)

    for (int base = blockIdx.x * 4; base < N; base += gridDim.x * 4) {
        int n = base + slot;
        bool valid = (n < N);
        if (valid) {
            aggs[slot * 64 + g] = g_AS[n * 64 + g];
            aggv[slot * 192 + g * 3 + 0] = g_AV[n * 192 + g * 3 + 0];
            aggv[slot * 192 + g * 3 + 1] = g_AV[n * 192 + g * 3 + 1];
            aggv[slot * 192 + g * 3 + 2] = g_AV[n * 192 + g * 3 + 2];
            nss[slot * 64 + g] = nfs[n * 64 + g];
            nvv[slot * 192 + g * 3 + 0] = nfv[n * 192 + g * 3 + 0];
            nvv[slot * 192 + g * 3 + 1] = nfv[n * 192 + g * 3 + 1];
            nvv[slot * 192 + g * 3 + 2] = nfv[n * 192 + g * 3 + 2];
        }
        __syncthreads();

        if (valid) {
            float sa = 0.f, va0 = 0.f, va1 = 0.f, va2 = 0.f;
            #pragma unroll 8
            for (int f = 0; f < 64; f++) {
                float wd1 = wds[f * 64 + g];
                float wd2 = wdv[f * 64 + g];
                sa  = fmaf(aggs[slot * 64 + f], wd1, sa);
                va0 = fmaf(aggv[slot * 192 + f * 3 + 0], wd2, va0);
                va1 = fmaf(aggv[slot * 192 + f * 3 + 1], wd2, va1);
                va2 = fmaf(aggv[slot * 192 + f * 3 + 2], wd2, va2);
            }
            sa *= inv; va0 *= inv; va1 *= inv; va2 *= inv;

            int sp = specie[n];
            const float* wss = wsym_s + sp * 192;  // [3][64]
            const float* wsv = wsym_v + sp * 128;  // [2][64]
            float ps = wss[g] * sa + wss[64 + g] * sa * sa
                     + wss[128 + g] * (va0 * va0 + va1 * va1 + va2 * va2);
            float cc = wsv[g] + wsv[64 + g] * sa;
            psb[slot * 64 + g] = ps;
            pvb[slot * 192 + g * 3 + 0] = cc * va0;
            pvb[slot * 192 + g * 3 + 1] = cc * va1;
            pvb[slot * 192 + g * 3 + 2] = cc * va2;
        }
        __syncthreads();

        if (valid) {
            int sp = specie[n];
            const float* sks = Wsk_s + (size_t)sp * 4096;
            const float* skv = Wsk_v + (size_t)sp * 4096;
            float fs = 0.f, fv0 = 0.f, fv1 = 0.f, fv2 = 0.f;
            #pragma unroll 8
            for (int f = 0; f < 64; f++) {
                float wl1 = wls[f * 64 + g];
                float sk1 = sks[f * 64 + g];
                fs = fmaf(psb[slot * 64 + f], wl1, fs);
                fs = fmaf(nss[slot * 64 + f], sk1, fs);
                float wl2 = wlv[f * 64 + g];
                float sk2 = skv[f * 64 + g];
                fv0 = fmaf(pvb[slot * 192 + f * 3 + 0], wl2, fv0);
                fv0 = fmaf(nvv[slot * 192 + f * 3 + 0], sk2, fv0);
                fv1 = fmaf(pvb[slot * 192 + f * 3 + 1], wl2, fv1);
                fv1 = fmaf(nvv[slot * 192 + f * 3 + 1], sk2, fv1);
                fv2 = fmaf(pvb[slot * 192 + f * 3 + 2], wl2, fv2);
                fv2 = fmaf(nvv[slot * 192 + f * 3 + 2], sk2, fv2);
            }
            fsO[n * 64 + g] = fs;
            fvO[n * 192 + g * 3 + 0] = fv0;
            fvO[n * 192 + g * 3 + 1] = fv1;
            fvO[n * 192 + g * 3 + 2] = fv2;
            aggs[slot * 64 + g] = fs;  // stage for readout
        }
        __syncthreads();

        if (valid && g == 0) {
            float acc = 0.f;
            #pragma unroll 8
            for (int f = 0; f < 64; f++) acc = fmaf(aggs[slot * 64 + f], wout[f], acc);
            out0[n] = acc;
        }
        __syncthreads();
    }
}

// ============================================================================
extern "C" void kernel_launch(void* const* d_in, const int* in_sizes, int n_in,
                              void* d_out, int out_size)
{
    const float* vectors  = (const float*)d_in[0];
    const float* nfs      = (const float*)d_in[1];
    const float* nfv      = (const float*)d_in[2];
    const float* RE       = (const float*)d_in[3];
    const float* Wus      = (const float*)d_in[4];
    const float* Wuv      = (const float*)d_in[5];
    const float* Wr1      = (const float*)d_in[6];
    const float* Wr2      = (const float*)d_in[7];
    const float* Wds      = (const float*)d_in[8];
    const float* Wdv      = (const float*)d_in[9];
    const float* wsym_s   = (const float*)d_in[10];
    const float* wsym_v   = (const float*)d_in[11];
    const float* WLs      = (const float*)d_in[12];
    const float* WLv      = (const float*)d_in[13];
    const float* Wsk_s    = (const float*)d_in[14];
    const float* Wsk_v    = (const float*)d_in[15];
    const float* Wout     = (const float*)d_in[16];
    const int*   specie   = (const int*)d_in[17];
    const int*   senders  = (const int*)d_in[18];
    const int*   receivers= (const int*)d_in[19];

    int N = in_sizes[1] / 64;
    int E = in_sizes[18];
    if (N > NN) N = NN;
    if (E > EE) E = EE;

    float* out0 = (float*)d_out;
    float* fsO  = out0 + N;
    float* fvO  = fsO + (size_t)N * 64;

    const int EDGE_SMEM = (20480 + 512 + 2048) * 4;   // 92160 B
    const int NODE_SMEM = 19520 * 4;                  // 78080 B
    cudaFuncSetAttribute(k_edge, cudaFuncAttributeMaxDynamicSharedMemorySize, EDGE_SMEM);
    cudaFuncSetAttribute(k_node, cudaFuncAttributeMaxDynamicSharedMemorySize, NODE_SMEM);

    k_up<<<1184, 256>>>(nfs, nfv, Wus, Wuv, N);
    k_edge<<<296, 256, EDGE_SMEM>>>(vectors, RE, Wr1, Wr2, senders, receivers, E);
    k_node<<<1184, 256, NODE_SMEM>>>(nfs, nfv, Wds, Wdv, wsym_s, wsym_v,
                                     WLs, WLv, Wsk_s, Wsk_v, Wout, specie,
                                     out0, fsO, fvO, N);
}

// round 2
// speedup vs baseline: 1.0280x; 1.0280x over previous
#include <cuda_runtime.h>
#include <math.h>

#define NN 50000
#define EE 800000

// ---- scratch (static device globals; allocation-free) ----
__device__ float g_S[NN * 64];          // up-projected scalars [N,64]
__device__ float g_V[NN * 192];         // up-projected vectors [N,64,3]
__device__ float g_A[NN * 256];         // packed aggregation [N][64][4] = (s,vx,vy,vz)
__device__ float g_W[(size_t)EE * 320]; // per-edge TP weights [E,320]

__device__ __forceinline__ unsigned f2tf32(float x) {
    unsigned r;
    asm("cvt.rna.tf32.f32 %0, %1;" : "=r"(r) : "f"(x));
    return r;
}

// ============================================================================
// Kernel A: linear-up + zero packed aggregation buffer.
// 256 thr = 8 warps; warp handles 4 nodes; lane owns channels (2l, 2l+1).
// Weights staged once per block as interleaved float4 (ws_c0, wv_c0, ws_c1, wv_c1)
// and reused across 4 nodes -> smem weight traffic /4 vs round 1.
// ============================================================================
__global__ __launch_bounds__(256) void k_up(
    const float* __restrict__ nfs, const float* __restrict__ nfv,
    const float* __restrict__ Wus, const float* __restrict__ Wuv, int N)
{
    extern __shared__ float su[];
    float4* wsv4 = (float4*)su;                        // 2048 float4 (32 KB)
    float*  s_in = su + 8192;                          // 8 warps * 4 * 64
    float4* v_in = (float4*)(su + 8192 + 2048);        // 8 warps * 4 * 64 float4

    int tid = threadIdx.x;
    const float2* us2 = (const float2*)Wus;
    const float2* uv2 = (const float2*)Wuv;
    for (int i = tid; i < 2048; i += 256) {
        float2 a = us2[i], b = uv2[i];
        wsv4[i] = make_float4(a.x, b.x, a.y, b.y);
    }
    __syncthreads();

    int warp = tid >> 5, lane = tid & 31;
    float*  ss = s_in + warp * 256;
    float4* vv = v_in + warp * 256;

    for (int base = blockIdx.x * 32 + warp * 4; base < N; base += gridDim.x * 32) {
        int nv = N - base; if (nv > 4) nv = 4;
        #pragma unroll
        for (int j = 0; j < 4; j++) {
            if (j < nv) {
                int n = base + j;
                float2 sv = *(const float2*)(nfs + (size_t)n * 64 + 2 * lane);
                ss[j * 64 + 2 * lane]     = sv.x;
                ss[j * 64 + 2 * lane + 1] = sv.y;
                const float2* vp = (const float2*)(nfv + (size_t)n * 192);
                float2 p0 = vp[lane * 3], p1 = vp[lane * 3 + 1], p2 = vp[lane * 3 + 2];
                vv[j * 64 + 2 * lane]     = make_float4(p0.x, p0.y, p1.x, 0.f);
                vv[j * 64 + 2 * lane + 1] = make_float4(p1.y, p2.x, p2.y, 0.f);
            }
        }
        __syncwarp();

        float acc[4][8];
        #pragma unroll
        for (int j = 0; j < 4; j++)
            #pragma unroll
            for (int q = 0; q < 8; q++) acc[j][q] = 0.f;

        #pragma unroll 4
        for (int f = 0; f < 64; f++) {
            float4 wq = wsv4[f * 32 + lane];
            #pragma unroll
            for (int j = 0; j < 4; j++) {
                float  sb = ss[j * 64 + f];
                float4 vb = vv[j * 64 + f];
                acc[j][0] = fmaf(sb, wq.x, acc[j][0]);
                acc[j][1] = fmaf(sb, wq.z, acc[j][1]);
                acc[j][2] = fmaf(vb.x, wq.y, acc[j][2]);
                acc[j][3] = fmaf(vb.y, wq.y, acc[j][3]);
                acc[j][4] = fmaf(vb.z, wq.y, acc[j][4]);
                acc[j][5] = fmaf(vb.x, wq.w, acc[j][5]);
                acc[j][6] = fmaf(vb.y, wq.w, acc[j][6]);
                acc[j][7] = fmaf(vb.z, wq.w, acc[j][7]);
            }
        }

        for (int j = 0; j < nv; j++) {
            int n = base + j;
            *(float2*)(g_S + (size_t)n * 64 + 2 * lane) = make_float2(acc[j][0], acc[j][1]);
            float2* vp = (float2*)(g_V + (size_t)n * 192);
            vp[lane * 3]     = make_float2(acc[j][2], acc[j][3]);
            vp[lane * 3 + 1] = make_float2(acc[j][4], acc[j][5]);
            vp[lane * 3 + 2] = make_float2(acc[j][6], acc[j][7]);
            float4* za = (float4*)(g_A + (size_t)n * 256);
            za[lane]      = make_float4(0.f, 0.f, 0.f, 0.f);
            za[32 + lane] = make_float4(0.f, 0.f, 0.f, 0.f);
        }
        __syncwarp();
    }
}

// ============================================================================
// Kernel B1: radial MLP via tensor cores (tf32 mma.sync m16n8k8).
// Per 64-edge tile: compute h = silu(RE@W_r1) into smem (tf32), then
// C[64,320] = h @ W_r2 with 8 warps (warp = 40-col strip), store to g_W.
// Bank-conflict-free strides: h stride 68, W_r2 stride 328.
// ============================================================================
__global__ __launch_bounds__(256) void k_gemm(
    const float* __restrict__ RE, const float* __restrict__ Wr1,
    const float* __restrict__ Wr2, int En)
{
    extern __shared__ float sg[];
    unsigned* wr2u = (unsigned*)sg;                 // 64*328
    unsigned* hu   = (unsigned*)(sg + 20992);       // 64*68
    float*    res  = sg + 20992 + 4352;             // 512
    float*    wr1s = res + 512;                     // 512

    int tid = threadIdx.x;
    for (int i = tid; i < 20480; i += 256) {
        int j = i / 320, n = i - j * 320;
        wr2u[j * 328 + n] = f2tf32(Wr2[i]);
    }
    for (int i = tid; i < 512; i += 256) wr1s[i] = Wr1[i];
    __syncthreads();

    int lane = tid & 31, warp = tid >> 5;
    int gid = lane >> 2, tig = lane & 3;
    int ntiles = (En + 63) >> 6;

    for (int t = blockIdx.x; t < ntiles; t += gridDim.x) {
        int e0 = t << 6;
        // stage RE tile
        for (int i = tid; i < 512; i += 256) {
            int e = e0 + (i >> 3);
            res[i] = (e < En) ? RE[(size_t)e * 8 + (i & 7)] : 0.f;
        }
        __syncthreads();
        // h = silu(res @ W_r1), tf32 in smem
        #pragma unroll
        for (int i = 0; i < 16; i++) {
            int idx = tid + 256 * i;
            int e = idx >> 6, j = idx & 63;
            const float* rr = res + e * 8;
            float a = 0.f;
            #pragma unroll
            for (int k = 0; k < 8; k++) a = fmaf(rr[k], wr1s[k * 64 + j], a);
            float hval = __fdividef(a, 1.f + __expf(-a));
            hu[e * 68 + j] = f2tf32(hval);
        }
        __syncthreads();

        float c[4][5][4];
        #pragma unroll
        for (int mt = 0; mt < 4; mt++)
            #pragma unroll
            for (int nt = 0; nt < 5; nt++)
                #pragma unroll
                for (int q = 0; q < 4; q++) c[mt][nt][q] = 0.f;

        #pragma unroll
        for (int ks = 0; ks < 8; ks++) {
            int kb = ks * 8;
            unsigned a[4][4];
            #pragma unroll
            for (int mt = 0; mt < 4; mt++) {
                int r0 = mt * 16 + gid;
                a[mt][0] = hu[r0 * 68 + kb + tig];
                a[mt][1] = hu[(r0 + 8) * 68 + kb + tig];
                a[mt][2] = hu[r0 * 68 + kb + tig + 4];
                a[mt][3] = hu[(r0 + 8) * 68 + kb + tig + 4];
            }
            #pragma unroll
            for (int nt = 0; nt < 5; nt++) {
                int col = warp * 40 + nt * 8 + gid;
                unsigned b0 = wr2u[(kb + tig) * 328 + col];
                unsigned b1 = wr2u[(kb + tig + 4) * 328 + col];
                #pragma unroll
                for (int mt = 0; mt < 4; mt++) {
                    asm volatile(
                        "mma.sync.aligned.m16n8k8.row.col.f32.tf32.tf32.f32 "
                        "{%0,%1,%2,%3}, {%4,%5,%6,%7}, {%8,%9}, {%0,%1,%2,%3};\n"
                        : "+f"(c[mt][nt][0]), "+f"(c[mt][nt][1]),
                          "+f"(c[mt][nt][2]), "+f"(c[mt][nt][3])
                        : "r"(a[mt][0]), "r"(a[mt][1]), "r"(a[mt][2]), "r"(a[mt][3]),
                          "r"(b0), "r"(b1));
                }
            }
        }
        // store
        #pragma unroll
        for (int mt = 0; mt < 4; mt++) {
            int r0 = e0 + mt * 16 + gid;
            #pragma unroll
            for (int nt = 0; nt < 5; nt++) {
                int col = warp * 40 + nt * 8 + 2 * tig;
                if (r0 < En)
                    *(float2*)(g_W + (size_t)r0 * 320 + col) =
                        make_float2(c[mt][nt][0], c[mt][nt][1]);
                if (r0 + 8 < En)
                    *(float2*)(g_W + (size_t)(r0 + 8) * 320 + col) =
                        make_float2(c[mt][nt][2], c[mt][nt][3]);
            }
        }
        __syncthreads();
    }
}

// ============================================================================
// Kernel B2: edge messages + vector-atomic scatter. One warp per edge.
// lane owns channels (2l, 2l+1); scatter = 2x red.global.add.v4.f32.
// ============================================================================
__global__ __launch_bounds__(256) void k_msg(
    const float* __restrict__ vectors, const int* __restrict__ senders,
    const int* __restrict__ receivers, int En)
{
    int lane = threadIdx.x & 31;
    int gw = (blockIdx.x << 3) + (threadIdx.x >> 5);
    int stride = gridDim.x << 3;

    for (int e = gw; e < En; e += stride) {
        const float2* wv2 = (const float2*)(g_W + (size_t)e * 320);
        float2 w0 = wv2[lane];
        float2 w1 = wv2[32 + lane];
        float2 w2 = wv2[64 + lane];
        float2 w3 = wv2[96 + lane];
        float2 w4 = wv2[128 + lane];

        int s = __ldg(senders + e);
        int r = __ldg(receivers + e);
        float vx = __ldg(vectors + (size_t)e * 3 + 0);
        float vy = __ldg(vectors + (size_t)e * 3 + 1);
        float vz = __ldg(vectors + (size_t)e * 3 + 2);
        float nrm = sqrtf(vx * vx + vy * vy + vz * vz);
        float ri = 1.f / (nrm + 1e-9f);
        float Y0 = vx * ri, Y1 = vy * ri, Y2 = vz * ri;

        float2 xs = __ldg((const float2*)(g_S + (size_t)s * 64) + lane);
        const float2* Vp = (const float2*)(g_V + (size_t)s * 192);
        float2 p0 = __ldg(Vp + lane * 3 + 0);
        float2 p1 = __ldg(Vp + lane * 3 + 1);
        float2 p2 = __ldg(Vp + lane * 3 + 2);
        float a0 = p0.x, a1 = p0.y, a2 = p1.x;
        float b0 = p1.y, b1 = p2.x, b2 = p2.y;

        float dota = a0 * Y0 + a1 * Y1 + a2 * Y2;
        float dotb = b0 * Y0 + b1 * Y1 + b2 * Y2;

        float msa = w0.x * xs.x + w3.x * dota;
        float msb = w0.y * xs.y + w3.y * dotb;

        float cxa0 = a1 * Y2 - a2 * Y1;
        float cxa1 = a2 * Y0 - a0 * Y2;
        float cxa2 = a0 * Y1 - a1 * Y0;
        float cxb0 = b1 * Y2 - b2 * Y1;
        float cxb1 = b2 * Y0 - b0 * Y2;
        float cxb2 = b0 * Y1 - b1 * Y0;

        float sa = w1.x * xs.x, sb = w1.y * xs.y;
        float mva0 = sa * Y0 + w2.x * a0 + w4.x * cxa0;
        float mva1 = sa * Y1 + w2.x * a1 + w4.x * cxa1;
        float mva2 = sa * Y2 + w2.x * a2 + w4.x * cxa2;
        float mvb0 = sb * Y0 + w2.y * b0 + w4.y * cxb0;
        float mvb1 = sb * Y1 + w2.y * b1 + w4.y * cxb1;
        float mvb2 = sb * Y2 + w2.y * b2 + w4.y * cxb2;

        float* base = g_A + (size_t)r * 256 + lane * 8;
        asm volatile("red.global.add.v4.f32 [%0], {%1,%2,%3,%4};"
                     :: "l"(base), "f"(msa), "f"(mva0), "f"(mva1), "f"(mva2)
                     : "memory");
        asm volatile("red.global.add.v4.f32 [%0], {%1,%2,%3,%4};"
                     :: "l"(base + 4), "f"(msb), "f"(mvb0), "f"(mvb1), "f"(mvb2)
                     : "memory");
    }
}

// ============================================================================
// Kernel C: node post-processing (unchanged math; reads packed g_A).
// ============================================================================
__global__ __launch_bounds__(256) void k_node(
    const float* __restrict__ nfs, const float* __restrict__ nfv,
    const float* __restrict__ Wds, const float* __restrict__ Wdv,
    const float* __restrict__ wsym_s, const float* __restrict__ wsym_v,
    const float* __restrict__ WLs, const float* __restrict__ WLv,
    const float* __restrict__ Wsk_s, const float* __restrict__ Wsk_v,
    const float* __restrict__ Wout, const int* __restrict__ specie,
    float* __restrict__ out0, float* __restrict__ fsO, float* __restrict__ fvO,
    int N)
{
    extern __shared__ float sm[];
    float* wds  = sm;
    float* wdv  = sm + 4096;
    float* wls  = sm + 8192;
    float* wlv  = sm + 12288;
    float* wout = sm + 16384;
    float* aggs = sm + 16448;
    float* aggv = sm + 16448 + 256;
    float* nss  = sm + 16448 + 1024;
    float* nvv  = sm + 16448 + 1280;
    float* psb  = sm + 16448 + 2048;
    float* pvb  = sm + 16448 + 2304;

    for (int i = threadIdx.x; i < 4096; i += 256) {
        wds[i] = Wds[i]; wdv[i] = Wdv[i]; wls[i] = WLs[i]; wlv[i] = WLv[i];
    }
    if (threadIdx.x < 64) wout[threadIdx.x] = Wout[threadIdx.x];
    __syncthreads();

    int slot = threadIdx.x >> 6;
    int g    = threadIdx.x & 63;
    const float inv = 0.25f;

    for (int base = blockIdx.x * 4; base < N; base += gridDim.x * 4) {
        int n = base + slot;
        bool valid = (n < N);
        if (valid) {
            float4 q = *((const float4*)g_A + (size_t)n * 64 + g);
            aggs[slot * 64 + g] = q.x;
            aggv[slot * 192 + g * 3 + 0] = q.y;
            aggv[slot * 192 + g * 3 + 1] = q.z;
            aggv[slot * 192 + g * 3 + 2] = q.w;
            nss[slot * 64 + g] = nfs[n * 64 + g];
            nvv[slot * 192 + g * 3 + 0] = nfv[n * 192 + g * 3 + 0];
            nvv[slot * 192 + g * 3 + 1] = nfv[n * 192 + g * 3 + 1];
            nvv[slot * 192 + g * 3 + 2] = nfv[n * 192 + g * 3 + 2];
        }
        __syncthreads();

        if (valid) {
            float sa = 0.f, va0 = 0.f, va1 = 0.f, va2 = 0.f;
            #pragma unroll 8
            for (int f = 0; f < 64; f++) {
                float wd1 = wds[f * 64 + g];
                float wd2 = wdv[f * 64 + g];
                sa  = fmaf(aggs[slot * 64 + f], wd1, sa);
                va0 = fmaf(aggv[slot * 192 + f * 3 + 0], wd2, va0);
                va1 = fmaf(aggv[slot * 192 + f * 3 + 1], wd2, va1);
                va2 = fmaf(aggv[slot * 192 + f * 3 + 2], wd2, va2);
            }
            sa *= inv; va0 *= inv; va1 *= inv; va2 *= inv;

            int sp = specie[n];
            const float* wss = wsym_s + sp * 192;
            const float* wsv = wsym_v + sp * 128;
            float ps = wss[g] * sa + wss[64 + g] * sa * sa
                     + wss[128 + g] * (va0 * va0 + va1 * va1 + va2 * va2);
            float cc = wsv[g] + wsv[64 + g] * sa;
            psb[slot * 64 + g] = ps;
            pvb[slot * 192 + g * 3 + 0] = cc * va0;
            pvb[slot * 192 + g * 3 + 1] = cc * va1;
            pvb[slot * 192 + g * 3 + 2] = cc * va2;
        }
        __syncthreads();

        if (valid) {
            int sp = specie[n];
            const float* sks = Wsk_s + (size_t)sp * 4096;
            const float* skv = Wsk_v + (size_t)sp * 4096;
            float fs = 0.f, fv0 = 0.f, fv1 = 0.f, fv2 = 0.f;
            #pragma unroll 8
            for (int f = 0; f < 64; f++) {
                float wl1 = wls[f * 64 + g];
                float sk1 = sks[f * 64 + g];
                fs = fmaf(psb[slot * 64 + f], wl1, fs);
                fs = fmaf(nss[slot * 64 + f], sk1, fs);
                float wl2 = wlv[f * 64 + g];
                float sk2 = skv[f * 64 + g];
                fv0 = fmaf(pvb[slot * 192 + f * 3 + 0], wl2, fv0);
                fv0 = fmaf(nvv[slot * 192 + f * 3 + 0], sk2, fv0);
                fv1 = fmaf(pvb[slot * 192 + f * 3 + 1], wl2, fv1);
                fv1 = fmaf(nvv[slot * 192 + f * 3 + 1], sk2, fv1);
                fv2 = fmaf(pvb[slot * 192 + f * 3 + 2], wl2, fv2);
                fv2 = fmaf(nvv[slot * 192 + f * 3 + 2], sk2, fv2);
            }
            fsO[n * 64 + g] = fs;
            fvO[n * 192 + g * 3 + 0] = fv0;
            fvO[n * 192 + g * 3 + 1] = fv1;
            fvO[n * 192 + g * 3 + 2] = fv2;
            aggs[slot * 64 + g] = fs;
        }
        __syncthreads();

        if (valid && g == 0) {
            float acc = 0.f;
            #pragma unroll 8
            for (int f = 0; f < 64; f++) acc = fmaf(aggs[slot * 64 + f], wout[f], acc);
            out0[n] = acc;
        }
        __syncthreads();
    }
}

// ============================================================================
extern "C" void kernel_launch(void* const* d_in, const int* in_sizes, int n_in,
                              void* d_out, int out_size)
{
    const float* vectors  = (const float*)d_in[0];
    const float* nfs      = (const float*)d_in[1];
    const float* nfv      = (const float*)d_in[2];
    const float* RE       = (const float*)d_in[3];
    const float* Wus      = (const float*)d_in[4];
    const float* Wuv      = (const float*)d_in[5];
    const float* Wr1      = (const float*)d_in[6];
    const float* Wr2      = (const float*)d_in[7];
    const float* Wds      = (const float*)d_in[8];
    const float* Wdv      = (const float*)d_in[9];
    const float* wsym_s   = (const float*)d_in[10];
    const float* wsym_v   = (const float*)d_in[11];
    const float* WLs      = (const float*)d_in[12];
    const float* WLv      = (const float*)d_in[13];
    const float* Wsk_s    = (const float*)d_in[14];
    const float* Wsk_v    = (const float*)d_in[15];
    const float* Wout     = (const float*)d_in[16];
    const int*   specie   = (const int*)d_in[17];
    const int*   senders  = (const int*)d_in[18];
    const int*   receivers= (const int*)d_in[19];

    int N = in_sizes[1] / 64;
    int E = in_sizes[18];
    if (N > NN) N = NN;
    if (E > EE) E = EE;

    float* out0 = (float*)d_out;
    float* fsO  = out0 + N;
    float* fvO  = fsO + (size_t)N * 64;

    const int UP_SMEM   = (8192 + 2048 + 8192) * 4;          // 73728 B
    const int GEMM_SMEM = (20992 + 4352 + 512 + 512) * 4;    // 105472 B
    const int NODE_SMEM = 19520 * 4;                         // 78080 B
    cudaFuncSetAttribute(k_up,   cudaFuncAttributeMaxDynamicSharedMemorySize, UP_SMEM);
    cudaFuncSetAttribute(k_gemm, cudaFuncAttributeMaxDynamicSharedMemorySize, GEMM_SMEM);
    cudaFuncSetAttribute(k_node, cudaFuncAttributeMaxDynamicSharedMemorySize, NODE_SMEM);

    k_up<<<296, 256, UP_SMEM>>>(nfs, nfv, Wus, Wuv, N);
    k_gemm<<<296, 256, GEMM_SMEM>>>(RE, Wr1, Wr2, E);
    k_msg<<<1184, 256>>>(vectors, senders, receivers, E);
    k_node<<<1184, 256, NODE_SMEM>>>(nfs, nfv, Wds, Wdv, wsym_s, wsym_v,
                                     WLs, WLv, Wsk_s, Wsk_v, Wout, specie,
                                     out0, fsO, fvO, N);
}

// round 6
// speedup vs baseline: 1.3207x; 1.2847x over previous
#include <cuda_runtime.h>
#include <math.h>

#define NN 50000
#define EE 800000
#define NSPEC 10

// ---- scratch (static device globals; allocation-free) ----
__device__ float g_S[NN * 64];          // up-projected scalars [N,64]
__device__ float g_V[NN * 192];         // up-projected vectors [N,64,3]
__device__ float g_A[NN * 256];         // packed aggregation [N][64][4] = (s,vx,vy,vz)
__device__ int   g_cnt[16];             // per-species node counts
__device__ int   g_bkt[NSPEC * NN];     // per-species node lists

__device__ __forceinline__ unsigned f2tf32(float x) {
    unsigned r;
    asm("cvt.rna.tf32.f32 %0, %1;" : "=r"(r) : "f"(x));
    return r;
}

// ============================================================================
// Species bucketing (warp-aggregated)
// ============================================================================
__global__ void k_zero_cnt() { if (threadIdx.x < 16) g_cnt[threadIdx.x] = 0; }

__global__ __launch_bounds__(256) void k_bucket(const int* __restrict__ specie, int N)
{
    int i = blockIdx.x * blockDim.x + threadIdx.x;
    if (i < N) {
        int sp = specie[i];
        unsigned mask = __match_any_sync(__activemask(), sp);
        int lane = threadIdx.x & 31;
        int leader = __ffs(mask) - 1;
        int rank = __popc(mask & ((1u << lane) - 1));
        int base = 0;
        if (lane == leader) base = atomicAdd(&g_cnt[sp], __popc(mask));
        base = __shfl_sync(mask, base, leader);
        g_bkt[sp * NN + base + rank] = i;
    }
}

// ============================================================================
// Kernel A: linear-up + zero packed aggregation buffer (round-2 design).
// ============================================================================
__global__ __launch_bounds__(256) void k_up(
    const float* __restrict__ nfs, const float* __restrict__ nfv,
    const float* __restrict__ Wus, const float* __restrict__ Wuv, int N)
{
    extern __shared__ float su[];
    float4* wsv4 = (float4*)su;                        // 2048 float4
    float*  s_in = su + 8192;
    float4* v_in = (float4*)(su + 8192 + 2048);

    int tid = threadIdx.x;
    const float2* us2 = (const float2*)Wus;
    const float2* uv2 = (const float2*)Wuv;
    for (int i = tid; i < 2048; i += 256) {
        float2 a = us2[i], b = uv2[i];
        wsv4[i] = make_float4(a.x, b.x, a.y, b.y);
    }
    __syncthreads();

    int warp = tid >> 5, lane = tid & 31;
    float*  ss = s_in + warp * 256;
    float4* vv = v_in + warp * 256;

    for (int base = blockIdx.x * 32 + warp * 4; base < N; base += gridDim.x * 32) {
        int nv = N - base; if (nv > 4) nv = 4;
        #pragma unroll
        for (int j = 0; j < 4; j++) {
            if (j < nv) {
                int n = base + j;
                float2 sv = *(const float2*)(nfs + (size_t)n * 64 + 2 * lane);
                ss[j * 64 + 2 * lane]     = sv.x;
                ss[j * 64 + 2 * lane + 1] = sv.y;
                const float2* vp = (const float2*)(nfv + (size_t)n * 192);
                float2 p0 = vp[lane * 3], p1 = vp[lane * 3 + 1], p2 = vp[lane * 3 + 2];
                vv[j * 64 + 2 * lane]     = make_float4(p0.x, p0.y, p1.x, 0.f);
                vv[j * 64 + 2 * lane + 1] = make_float4(p1.y, p2.x, p2.y, 0.f);
            }
        }
        __syncwarp();

        float acc[4][8];
        #pragma unroll
        for (int j = 0; j < 4; j++)
            #pragma unroll
            for (int q = 0; q < 8; q++) acc[j][q] = 0.f;

        #pragma unroll 4
        for (int f = 0; f < 64; f++) {
            float4 wq = wsv4[f * 32 + lane];
            #pragma unroll
            for (int j = 0; j < 4; j++) {
                float  sb = ss[j * 64 + f];
                float4 vb = vv[j * 64 + f];
                acc[j][0] = fmaf(sb, wq.x, acc[j][0]);
                acc[j][1] = fmaf(sb, wq.z, acc[j][1]);
                acc[j][2] = fmaf(vb.x, wq.y, acc[j][2]);
                acc[j][3] = fmaf(vb.y, wq.y, acc[j][3]);
                acc[j][4] = fmaf(vb.z, wq.y, acc[j][4]);
                acc[j][5] = fmaf(vb.x, wq.w, acc[j][5]);
                acc[j][6] = fmaf(vb.y, wq.w, acc[j][6]);
                acc[j][7] = fmaf(vb.z, wq.w, acc[j][7]);
            }
        }

        for (int j = 0; j < nv; j++) {
            int n = base + j;
            *(float2*)(g_S + (size_t)n * 64 + 2 * lane) = make_float2(acc[j][0], acc[j][1]);
            float2* vp = (float2*)(g_V + (size_t)n * 192);
            vp[lane * 3]     = make_float2(acc[j][2], acc[j][3]);
            vp[lane * 3 + 1] = make_float2(acc[j][4], acc[j][5]);
            vp[lane * 3 + 2] = make_float2(acc[j][6], acc[j][7]);
            float4* za = (float4*)(g_A + (size_t)n * 256);
            za[lane]      = make_float4(0.f, 0.f, 0.f, 0.f);
            za[32 + lane] = make_float4(0.f, 0.f, 0.f, 0.f);
        }
        __syncwarp();
    }
}

// ============================================================================
// Kernel B (FUSED): radial MLP on tensor cores -> C in SMEM -> messages ->
// vector-atomic scatter. 64-edge tiles, 256 threads, 1 block/SM.
// ============================================================================
__global__ __launch_bounds__(256) void k_edge(
    const float* __restrict__ RE, const float* __restrict__ Wr1,
    const float* __restrict__ Wr2, const float* __restrict__ vectors,
    const int* __restrict__ senders, const int* __restrict__ receivers, int En)
{
    extern __shared__ float sg[];
    unsigned* wr2u = (unsigned*)sg;                 // 64*328
    float*    csm  = sg + 20992;                    // 64*328
    unsigned* hu   = (unsigned*)(sg + 41984);       // 64*68
    float*    res  = sg + 41984 + 4352;             // 512
    float*    wr1s = res + 512;                     // 512

    int tid = threadIdx.x;
    for (int i = tid; i < 20480; i += 256) {
        int j = i / 320, n = i - j * 320;
        wr2u[j * 328 + n] = f2tf32(Wr2[i]);
    }
    for (int i = tid; i < 512; i += 256) wr1s[i] = Wr1[i];
    __syncthreads();

    int lane = tid & 31, warp = tid >> 5;
    int gid = lane >> 2, tig = lane & 3;
    int ntiles = (En + 63) >> 6;

    for (int t = blockIdx.x; t < ntiles; t += gridDim.x) {
        int e0 = t << 6;
        // stage RE tile
        for (int i = tid; i < 512; i += 256) {
            int e = e0 + (i >> 3);
            res[i] = (e < En) ? RE[(size_t)e * 8 + (i & 7)] : 0.f;
        }
        __syncthreads();
        // h = silu(res @ W_r1) as tf32
        #pragma unroll
        for (int i = 0; i < 16; i++) {
            int idx = tid + 256 * i;
            int e = idx >> 6, j = idx & 63;
            const float* rr = res + e * 8;
            float a = 0.f;
            #pragma unroll
            for (int k = 0; k < 8; k++) a = fmaf(rr[k], wr1s[k * 64 + j], a);
            float hval = __fdividef(a, 1.f + __expf(-a));
            hu[e * 68 + j] = f2tf32(hval);
        }
        __syncthreads();

        // MMA: C[64,320] = h @ W_r2, warp owns 40-col strip
        float c[4][5][4];
        #pragma unroll
        for (int mt = 0; mt < 4; mt++)
            #pragma unroll
            for (int nt = 0; nt < 5; nt++)
                #pragma unroll
                for (int q = 0; q < 4; q++) c[mt][nt][q] = 0.f;

        #pragma unroll
        for (int ks = 0; ks < 8; ks++) {
            int kb = ks * 8;
            unsigned a[4][4];
            #pragma unroll
            for (int mt = 0; mt < 4; mt++) {
                int r0 = mt * 16 + gid;
                a[mt][0] = hu[r0 * 68 + kb + tig];
                a[mt][1] = hu[(r0 + 8) * 68 + kb + tig];
                a[mt][2] = hu[r0 * 68 + kb + tig + 4];
                a[mt][3] = hu[(r0 + 8) * 68 + kb + tig + 4];
            }
            #pragma unroll
            for (int nt = 0; nt < 5; nt++) {
                int col = warp * 40 + nt * 8 + gid;
                unsigned b0 = wr2u[(kb + tig) * 328 + col];
                unsigned b1 = wr2u[(kb + tig + 4) * 328 + col];
                #pragma unroll
                for (int mt = 0; mt < 4; mt++) {
                    asm volatile(
                        "mma.sync.aligned.m16n8k8.row.col.f32.tf32.tf32.f32 "
                        "{%0,%1,%2,%3}, {%4,%5,%6,%7}, {%8,%9}, {%0,%1,%2,%3};\n"
                        : "+f"(c[mt][nt][0]), "+f"(c[mt][nt][1]),
                          "+f"(c[mt][nt][2]), "+f"(c[mt][nt][3])
                        : "r"(a[mt][0]), "r"(a[mt][1]), "r"(a[mt][2]), "r"(a[mt][3]),
                          "r"(b0), "r"(b1));
                }
            }
        }
        // store C fragments into smem
        #pragma unroll
        for (int mt = 0; mt < 4; mt++) {
            int r0 = mt * 16 + gid;
            #pragma unroll
            for (int nt = 0; nt < 5; nt++) {
                int col = warp * 40 + nt * 8 + 2 * tig;
                *(float2*)(csm + r0 * 328 + col) = make_float2(c[mt][nt][0], c[mt][nt][1]);
                *(float2*)(csm + (r0 + 8) * 328 + col) = make_float2(c[mt][nt][2], c[mt][nt][3]);
            }
        }
        __syncthreads();

        // messages: warp handles 8 edges, lane owns channels (2l, 2l+1)
        #pragma unroll 2
        for (int i = 0; i < 8; i++) {
            int el = warp * 8 + i;
            int e = e0 + el;
            if (e < En) {
                const float* cw = csm + el * 328;
                float2 w0 = *(const float2*)(cw + 2 * lane);
                float2 w1 = *(const float2*)(cw + 64 + 2 * lane);
                float2 w2 = *(const float2*)(cw + 128 + 2 * lane);
                float2 w3 = *(const float2*)(cw + 192 + 2 * lane);
                float2 w4 = *(const float2*)(cw + 256 + 2 * lane);

                int s = __ldg(senders + e);
                int r = __ldg(receivers + e);
                float vx = __ldg(vectors + (size_t)e * 3 + 0);
                float vy = __ldg(vectors + (size_t)e * 3 + 1);
                float vz = __ldg(vectors + (size_t)e * 3 + 2);
                float nrm = sqrtf(vx * vx + vy * vy + vz * vz);
                float ri = 1.f / (nrm + 1e-9f);
                float Y0 = vx * ri, Y1 = vy * ri, Y2 = vz * ri;

                float2 xs = __ldg((const float2*)(g_S + (size_t)s * 64) + lane);
                const float2* Vp = (const float2*)(g_V + (size_t)s * 192);
                float2 p0 = __ldg(Vp + lane * 3 + 0);
                float2 p1 = __ldg(Vp + lane * 3 + 1);
                float2 p2 = __ldg(Vp + lane * 3 + 2);
                float a0 = p0.x, a1 = p0.y, a2 = p1.x;
                float b0 = p1.y, b1 = p2.x, b2 = p2.y;

                float dota = a0 * Y0 + a1 * Y1 + a2 * Y2;
                float dotb = b0 * Y0 + b1 * Y1 + b2 * Y2;

                float msa = w0.x * xs.x + w3.x * dota;
                float msb = w0.y * xs.y + w3.y * dotb;

                float cxa0 = a1 * Y2 - a2 * Y1;
                float cxa1 = a2 * Y0 - a0 * Y2;
                float cxa2 = a0 * Y1 - a1 * Y0;
                float cxb0 = b1 * Y2 - b2 * Y1;
                float cxb1 = b2 * Y0 - b0 * Y2;
                float cxb2 = b0 * Y1 - b1 * Y0;

                float sa = w1.x * xs.x, sb = w1.y * xs.y;
                float mva0 = sa * Y0 + w2.x * a0 + w4.x * cxa0;
                float mva1 = sa * Y1 + w2.x * a1 + w4.x * cxa1;
                float mva2 = sa * Y2 + w2.x * a2 + w4.x * cxa2;
                float mvb0 = sb * Y0 + w2.y * b0 + w4.y * cxb0;
                float mvb1 = sb * Y1 + w2.y * b1 + w4.y * cxb1;
                float mvb2 = sb * Y2 + w2.y * b2 + w4.y * cxb2;

                float* base = g_A + (size_t)r * 256 + lane * 8;
                asm volatile("red.global.add.v4.f32 [%0], {%1,%2,%3,%4};"
                             :: "l"(base), "f"(msa), "f"(mva0), "f"(mva1), "f"(mva2)
                             : "memory");
                asm volatile("red.global.add.v4.f32 [%0], {%1,%2,%3,%4};"
                             :: "l"(base + 4), "f"(msb), "f"(mvb0), "f"(mvb1), "f"(mvb2)
                             : "memory");
            }
        }
        __syncthreads();
    }
}

// ============================================================================
// Kernel C: node post. Blocks own ONE species (skip weights staged in smem).
// Warp = 4 nodes, lane = channel pair. All operand reads are broadcasts or
// float4 weight loads amortized over 4 nodes.
// grid = (BPS, NSPEC)
// ============================================================================
__global__ __launch_bounds__(256) void k_node(
    const float* __restrict__ nfs, const float* __restrict__ nfv,
    const float* __restrict__ Wds, const float* __restrict__ Wdv,
    const float* __restrict__ wsym_s, const float* __restrict__ wsym_v,
    const float* __restrict__ WLs, const float* __restrict__ WLv,
    const float* __restrict__ Wsk_s, const float* __restrict__ Wsk_v,
    const float* __restrict__ Wout,
    float* __restrict__ out0, float* __restrict__ fsO, float* __restrict__ fvO)
{
    extern __shared__ float sn[];
    float4* wd4  = (float4*)sn;                    // 2048 (ds0,dv0,ds1,dv1)
    float4* wl4  = (float4*)(sn + 8192);           // 2048 (ls0,lv0,ls1,lv1)
    float4* sk4  = (float4*)(sn + 16384);          // 2048 (ss0,sv0,ss1,sv1)
    float*  wsym = sn + 24576;                     // 320: ws0,ws1,ws2,wv0,wv1
    float*  wout = sn + 24896;                     // 64
    float4* aggb = (float4*)(sn + 24960);          // 8 warps * 256
    float4* nfb  = (float4*)(sn + 24960 + 8192);   // 8 * 256
    float4* psb  = (float4*)(sn + 24960 + 16384);  // 8 * 256

    int tid = threadIdx.x;
    int sp = blockIdx.y;

    {
        const float2* ds2 = (const float2*)Wds;
        const float2* dv2 = (const float2*)Wdv;
        const float2* ls2 = (const float2*)WLs;
        const float2* lv2 = (const float2*)WLv;
        const float2* ss2 = (const float2*)(Wsk_s + (size_t)sp * 4096);
        const float2* sv2 = (const float2*)(Wsk_v + (size_t)sp * 4096);
        for (int i = tid; i < 2048; i += 256) {
            float2 a = ds2[i], b = dv2[i];
            wd4[i] = make_float4(a.x, b.x, a.y, b.y);
            float2 cl = ls2[i], dl = lv2[i];
            wl4[i] = make_float4(cl.x, dl.x, cl.y, dl.y);
            float2 e = ss2[i], f = sv2[i];
            sk4[i] = make_float4(e.x, f.x, e.y, f.y);
        }
        for (int i = tid; i < 192; i += 256) wsym[i] = wsym_s[sp * 192 + i];
        for (int i = tid; i < 128; i += 256) wsym[192 + i] = wsym_v[sp * 128 + i];
        if (tid < 64) wout[tid] = Wout[tid];
    }
    __syncthreads();

    int warp = tid >> 5, lane = tid & 31;
    float4* ab = aggb + warp * 256;
    float4* nb = nfb + warp * 256;
    float4* pb = psb + warp * 256;
    int cnt = g_cnt[sp];
    const int* lst = g_bkt + sp * NN;
    const float* ws0 = wsym, *ws1 = wsym + 64, *ws2 = wsym + 128;
    const float* wv0 = wsym + 192, *wv1 = wsym + 256;

    for (int base = blockIdx.x * 32 + warp * 4; base < cnt; base += gridDim.x * 32) {
        int nv = cnt - base; if (nv > 4) nv = 4;
        int nn[4];
        #pragma unroll
        for (int j = 0; j < 4; j++) nn[j] = lst[base + ((j < nv) ? j : 0)];

        #pragma unroll
        for (int j = 0; j < 4; j++) {
            int n = nn[j];
            const float4* ga = (const float4*)g_A + (size_t)n * 64;
            ab[j * 64 + 2 * lane]     = ga[2 * lane];
            ab[j * 64 + 2 * lane + 1] = ga[2 * lane + 1];
            float2 sv = *(const float2*)(nfs + (size_t)n * 64 + 2 * lane);
            const float2* vp = (const float2*)(nfv + (size_t)n * 192);
            float2 p0 = vp[lane * 3], p1 = vp[lane * 3 + 1], p2 = vp[lane * 3 + 2];
            nb[j * 64 + 2 * lane]     = make_float4(sv.x, p0.x, p0.y, p1.x);
            nb[j * 64 + 2 * lane + 1] = make_float4(sv.y, p1.y, p2.x, p2.y);
        }
        __syncwarp();

        // ---- loop1: down-projection * 0.25 ----
        float acc[4][8];
        #pragma unroll
        for (int j = 0; j < 4; j++)
            #pragma unroll
            for (int q = 0; q < 8; q++) acc[j][q] = 0.f;

        #pragma unroll 4
        for (int f = 0; f < 64; f++) {
            float4 wq = wd4[f * 32 + lane];
            #pragma unroll
            for (int j = 0; j < 4; j++) {
                float4 a = ab[j * 64 + f];
                acc[j][0] = fmaf(a.x, wq.x, acc[j][0]);
                acc[j][1] = fmaf(a.y, wq.y, acc[j][1]);
                acc[j][2] = fmaf(a.z, wq.y, acc[j][2]);
                acc[j][3] = fmaf(a.w, wq.y, acc[j][3]);
                acc[j][4] = fmaf(a.x, wq.z, acc[j][4]);
                acc[j][5] = fmaf(a.y, wq.w, acc[j][5]);
                acc[j][6] = fmaf(a.z, wq.w, acc[j][6]);
                acc[j][7] = fmaf(a.w, wq.w, acc[j][7]);
            }
        }

        int c0 = 2 * lane, c1 = 2 * lane + 1;
        #pragma unroll
        for (int j = 0; j < 4; j++) {
            float sa0 = acc[j][0] * 0.25f, va0 = acc[j][1] * 0.25f;
            float va1 = acc[j][2] * 0.25f, va2 = acc[j][3] * 0.25f;
            float sa1 = acc[j][4] * 0.25f, vb0 = acc[j][5] * 0.25f;
            float vb1 = acc[j][6] * 0.25f, vb2 = acc[j][7] * 0.25f;
            float ps0 = ws0[c0] * sa0 + ws1[c0] * sa0 * sa0
                      + ws2[c0] * (va0 * va0 + va1 * va1 + va2 * va2);
            float cc0 = wv0[c0] + wv1[c0] * sa0;
            float ps1 = ws0[c1] * sa1 + ws1[c1] * sa1 * sa1
                      + ws2[c1] * (vb0 * vb0 + vb1 * vb1 + vb2 * vb2);
            float cc1 = wv0[c1] + wv1[c1] * sa1;
            pb[j * 64 + c0] = make_float4(ps0, cc0 * va0, cc0 * va1, cc0 * va2);
            pb[j * 64 + c1] = make_float4(ps1, cc1 * vb0, cc1 * vb1, cc1 * vb2);
        }
        __syncwarp();

        // ---- loop2: linear + species skip ----
        float a2c[4][8];
        #pragma unroll
        for (int j = 0; j < 4; j++)
            #pragma unroll
            for (int q = 0; q < 8; q++) a2c[j][q] = 0.f;

        #pragma unroll 4
        for (int f = 0; f < 64; f++) {
            float4 wl = wl4[f * 32 + lane];
            float4 sk = sk4[f * 32 + lane];
            #pragma unroll
            for (int j = 0; j < 4; j++) {
                float4 p = pb[j * 64 + f];
                float4 q = nb[j * 64 + f];
                a2c[j][0] = fmaf(p.x, wl.x, fmaf(q.x, sk.x, a2c[j][0]));
                a2c[j][1] = fmaf(p.y, wl.y, fmaf(q.y, sk.y, a2c[j][1]));
                a2c[j][2] = fmaf(p.z, wl.y, fmaf(q.z, sk.y, a2c[j][2]));
                a2c[j][3] = fmaf(p.w, wl.y, fmaf(q.w, sk.y, a2c[j][3]));
                a2c[j][4] = fmaf(p.x, wl.z, fmaf(q.x, sk.z, a2c[j][4]));
                a2c[j][5] = fmaf(p.y, wl.w, fmaf(q.y, sk.w, a2c[j][5]));
                a2c[j][6] = fmaf(p.z, wl.w, fmaf(q.z, sk.w, a2c[j][6]));
                a2c[j][7] = fmaf(p.w, wl.w, fmaf(q.w, sk.w, a2c[j][7]));
            }
        }

        #pragma unroll
        for (int j = 0; j < 4; j++) {
            int n = nn[j];
            float r = a2c[j][0] * wout[c0] + a2c[j][4] * wout[c1];
            #pragma unroll
            for (int off = 16; off > 0; off >>= 1)
                r += __shfl_xor_sync(0xffffffffu, r, off);
            if (j < nv) {
                *(float2*)(fsO + (size_t)n * 64 + c0) = make_float2(a2c[j][0], a2c[j][4]);
                float* vb = fvO + (size_t)n * 192 + 6 * lane;
                *(float2*)(vb)     = make_float2(a2c[j][1], a2c[j][2]);
                *(float2*)(vb + 2) = make_float2(a2c[j][3], a2c[j][5]);
                *(float2*)(vb + 4) = make_float2(a2c[j][6], a2c[j][7]);
                if (lane == 0) out0[n] = r;
            }
        }
        __syncwarp();
    }
}

// ============================================================================
extern "C" void kernel_launch(void* const* d_in, const int* in_sizes, int n_in,
                              void* d_out, int out_size)
{
    const float* vectors  = (const float*)d_in[0];
    const float* nfs      = (const float*)d_in[1];
    const float* nfv      = (const float*)d_in[2];
    const float* RE       = (const float*)d_in[3];
    const float* Wus      = (const float*)d_in[4];
    const float* Wuv      = (const float*)d_in[5];
    const float* Wr1      = (const float*)d_in[6];
    const float* Wr2      = (const float*)d_in[7];
    const float* Wds      = (const float*)d_in[8];
    const float* Wdv      = (const float*)d_in[9];
    const float* wsym_s   = (const float*)d_in[10];
    const float* wsym_v   = (const float*)d_in[11];
    const float* WLs      = (const float*)d_in[12];
    const float* WLv      = (const float*)d_in[13];
    const float* Wsk_s    = (const float*)d_in[14];
    const float* Wsk_v    = (const float*)d_in[15];
    const float* Wout     = (const float*)d_in[16];
    const int*   specie   = (const int*)d_in[17];
    const int*   senders  = (const int*)d_in[18];
    const int*   receivers= (const int*)d_in[19];

    int N = in_sizes[1] / 64;
    int E = in_sizes[18];
    if (N > NN) N = NN;
    if (E > EE) E = EE;

    float* out0 = (float*)d_out;
    float* fsO  = out0 + N;
    float* fvO  = fsO + (size_t)N * 64;

    const int UP_SMEM   = (8192 + 2048 + 8192) * 4;                 // 73728 B
    const int EDGE_SMEM = (20992 + 20992 + 4352 + 512 + 512) * 4;   // 189440 B
    const int NODE_SMEM = (24960 + 3 * 8192) * 4;                   // 198144 B
    cudaFuncSetAttribute(k_up,   cudaFuncAttributeMaxDynamicSharedMemorySize, UP_SMEM);
    cudaFuncSetAttribute(k_edge, cudaFuncAttributeMaxDynamicSharedMemorySize, EDGE_SMEM);
    cudaFuncSetAttribute(k_node, cudaFuncAttributeMaxDynamicSharedMemorySize, NODE_SMEM);

    k_zero_cnt<<<1, 32>>>();
    k_bucket<<<(N + 255) / 256, 256>>>(specie, N);
    k_up<<<296, 256, UP_SMEM>>>(nfs, nfv, Wus, Wuv, N);
    k_edge<<<148, 256, EDGE_SMEM>>>(RE, Wr1, Wr2, vectors, senders, receivers, E);
    k_node<<<dim3(15, NSPEC), 256, NODE_SMEM>>>(nfs, nfv, Wds, Wdv,
                                                wsym_s, wsym_v, WLs, WLv,
                                                Wsk_s, Wsk_v, Wout,
                                                out0, fsO, fvO);
}